// round 1
// baseline (speedup 1.0000x reference)
#include <cuda_runtime.h>
#include <cstdint>

#define NN 50000
#define NE 800000
#define FIN 256
#define HD 128

// ---------------- scratch (no allocations allowed) ----------------
__device__ float g_S[(size_t)NN * HD];   // support buffer (X@W or H@W)
__device__ float g_H[(size_t)NN * HD];   // hidden layer output
__device__ int   g_rowptr[NN + 1];
__device__ int   g_fill[NN];
__device__ int   g_col[NE];
__device__ float g_val[NE];

// ---------------- CSR build ----------------
__global__ void zero_rowptr_kernel() {
    int i = blockIdx.x * blockDim.x + threadIdx.x;
    if (i <= NN) g_rowptr[i] = 0;
}

__global__ void hist_kernel(const int* __restrict__ rows) {
    int e = blockIdx.x * blockDim.x + threadIdx.x;
    if (e < NE) atomicAdd(&g_rowptr[rows[e] + 1], 1);
}

// single-block inclusive scan over g_rowptr[0..NN]; also writes g_fill[r]=rowptr[r]
__global__ void scan_kernel() {
    __shared__ int warp_sums[32];
    __shared__ int s_carry;
    const int tid = threadIdx.x;
    const int lane = tid & 31;
    const int wid = tid >> 5;
    if (tid == 0) s_carry = 0;
    __syncthreads();
    for (int base = 0; base < NN + 1; base += 1024) {
        int i = base + tid;
        int v = (i <= NN) ? g_rowptr[i] : 0;
        int x = v;
        #pragma unroll
        for (int off = 1; off < 32; off <<= 1) {
            int t = __shfl_up_sync(0xffffffffu, x, off);
            if (lane >= off) x += t;
        }
        if (lane == 31) warp_sums[wid] = x;
        __syncthreads();
        if (wid == 0) {
            int w = warp_sums[lane];
            #pragma unroll
            for (int off = 1; off < 32; off <<= 1) {
                int t = __shfl_up_sync(0xffffffffu, w, off);
                if (lane >= off) w += t;
            }
            warp_sums[lane] = w;
        }
        __syncthreads();
        int prefix = (wid > 0 ? warp_sums[wid - 1] : 0) + s_carry;
        int out = x + prefix;  // inclusive scan value at i == rowptr[i]
        if (i <= NN) {
            g_rowptr[i] = out;
            if (i < NN) g_fill[i] = out;  // start cursor for scatter
        }
        __syncthreads();
        if (tid == 1023) s_carry = out;
        __syncthreads();
    }
}

__global__ void scatter_kernel(const int* __restrict__ rows,
                               const int* __restrict__ cols,
                               const float* __restrict__ vals) {
    int e = blockIdx.x * blockDim.x + threadIdx.x;
    if (e < NE) {
        int r = rows[e];
        int p = atomicAdd(&g_fill[r], 1);
        g_col[p] = cols[e];
        g_val[p] = vals[e];
    }
}

// ---------------- dense GEMM: C[M x 128] = A[M x K] @ B[K x 128] ----------------
// 128x128 block tile, BK=16, 256 threads, 8x8 per-thread micro-tile
template <int K>
__global__ __launch_bounds__(256, 2)
void sgemm_n128(const float* __restrict__ A, const float* __restrict__ B,
                float* __restrict__ C, int M) {
    __shared__ float As[16][128];
    __shared__ float Bs[16][128];
    const int tid = threadIdx.x;
    const int tx = tid & 15;        // 0..15 -> 8 cols each
    const int ty = tid >> 4;        // 0..15 -> 8 rows each
    const int m0 = blockIdx.x * 128;

    float acc[8][8];
    #pragma unroll
    for (int i = 0; i < 8; i++)
        #pragma unroll
        for (int j = 0; j < 8; j++) acc[i][j] = 0.f;

    for (int kb = 0; kb < K; kb += 16) {
        // load A tile (128 rows x 16 cols), transpose into As[k][m]
        #pragma unroll
        for (int l = 0; l < 2; l++) {
            int f = tid + l * 256;      // 0..511 float4s
            int row = f >> 2;           // 0..127
            int c4 = f & 3;             // 0..3
            int gm = m0 + row;
            float4 v = make_float4(0.f, 0.f, 0.f, 0.f);
            if (gm < M) v = *(const float4*)(A + (size_t)gm * K + kb + c4 * 4);
            As[c4 * 4 + 0][row] = v.x;
            As[c4 * 4 + 1][row] = v.y;
            As[c4 * 4 + 2][row] = v.z;
            As[c4 * 4 + 3][row] = v.w;
        }
        // load B tile (16 rows x 128 cols)
        #pragma unroll
        for (int l = 0; l < 2; l++) {
            int f = tid + l * 256;      // 0..511 float4s
            int row = f >> 5;           // 0..15
            int c = f & 31;             // 0..31
            *(float4*)&Bs[row][c * 4] =
                *(const float4*)(B + (size_t)(kb + row) * 128 + c * 4);
        }
        __syncthreads();
        #pragma unroll
        for (int kk = 0; kk < 16; kk++) {
            float a[8], b[8];
            float4 a0 = *(const float4*)&As[kk][ty * 8];
            float4 a1 = *(const float4*)&As[kk][ty * 8 + 4];
            float4 b0 = *(const float4*)&Bs[kk][tx * 8];
            float4 b1 = *(const float4*)&Bs[kk][tx * 8 + 4];
            a[0]=a0.x; a[1]=a0.y; a[2]=a0.z; a[3]=a0.w;
            a[4]=a1.x; a[5]=a1.y; a[6]=a1.z; a[7]=a1.w;
            b[0]=b0.x; b[1]=b0.y; b[2]=b0.z; b[3]=b0.w;
            b[4]=b1.x; b[5]=b1.y; b[6]=b1.z; b[7]=b1.w;
            #pragma unroll
            for (int i = 0; i < 8; i++)
                #pragma unroll
                for (int j = 0; j < 8; j++)
                    acc[i][j] += a[i] * b[j];
        }
        __syncthreads();
    }
    // store
    #pragma unroll
    for (int i = 0; i < 8; i++) {
        int gm = m0 + ty * 8 + i;
        if (gm < M) {
            *(float4*)&C[(size_t)gm * 128 + tx * 8] =
                make_float4(acc[i][0], acc[i][1], acc[i][2], acc[i][3]);
            *(float4*)&C[(size_t)gm * 128 + tx * 8 + 4] =
                make_float4(acc[i][4], acc[i][5], acc[i][6], acc[i][7]);
        }
    }
}

// ---------------- SPMM (CSR gather) + bias + relu ----------------
// one warp per row, float4 per lane (32 lanes x 4 = 128 cols)
__global__ __launch_bounds__(256)
void spmm_relu_kernel(const float* __restrict__ S, const float* __restrict__ bias,
                      float* __restrict__ out) {
    int gw = (blockIdx.x * blockDim.x + threadIdx.x) >> 5;
    int lane = threadIdx.x & 31;
    if (gw >= NN) return;
    int s = g_rowptr[gw];
    int e = g_rowptr[gw + 1];
    float4 a0 = make_float4(0.f, 0.f, 0.f, 0.f);
    float4 a1 = make_float4(0.f, 0.f, 0.f, 0.f);
    int i = s;
    for (; i + 2 <= e; i += 2) {
        int c0 = g_col[i];
        int c1 = g_col[i + 1];
        float v0 = g_val[i];
        float v1 = g_val[i + 1];
        float4 x0 = *(const float4*)(S + (size_t)c0 * 128 + lane * 4);
        float4 x1 = *(const float4*)(S + (size_t)c1 * 128 + lane * 4);
        a0.x += v0 * x0.x; a0.y += v0 * x0.y; a0.z += v0 * x0.z; a0.w += v0 * x0.w;
        a1.x += v1 * x1.x; a1.y += v1 * x1.y; a1.z += v1 * x1.z; a1.w += v1 * x1.w;
    }
    if (i < e) {
        int c0 = g_col[i];
        float v0 = g_val[i];
        float4 x0 = *(const float4*)(S + (size_t)c0 * 128 + lane * 4);
        a0.x += v0 * x0.x; a0.y += v0 * x0.y; a0.z += v0 * x0.z; a0.w += v0 * x0.w;
    }
    float4 b = *(const float4*)(bias + lane * 4);
    float4 r;
    r.x = fmaxf(a0.x + a1.x + b.x, 0.f);
    r.y = fmaxf(a0.y + a1.y + b.y, 0.f);
    r.z = fmaxf(a0.z + a1.z + b.z, 0.f);
    r.w = fmaxf(a0.w + a1.w + b.w, 0.f);
    *(float4*)(out + (size_t)gw * 128 + lane * 4) = r;
}

// ---------------- launch ----------------
extern "C" void kernel_launch(void* const* d_in, const int* in_sizes, int n_in,
                              void* d_out, int out_size) {
    const float* features = (const float*)d_in[0];
    const int*   adj_rows = (const int*)d_in[1];
    const int*   adj_cols = (const int*)d_in[2];
    const float* adj_vals = (const float*)d_in[3];
    const float* W1 = (const float*)d_in[4];
    const float* b1 = (const float*)d_in[5];
    const float* W2 = (const float*)d_in[6];
    const float* b2 = (const float*)d_in[7];
    float* out = (float*)d_out;

    float* dS;  cudaGetSymbolAddress((void**)&dS, g_S);
    float* dH;  cudaGetSymbolAddress((void**)&dH, g_H);

    // CSR build
    zero_rowptr_kernel<<<(NN + 1 + 255) / 256, 256>>>();
    hist_kernel<<<(NE + 255) / 256, 256>>>(adj_rows);
    scan_kernel<<<1, 1024>>>();
    scatter_kernel<<<(NE + 255) / 256, 256>>>(adj_rows, adj_cols, adj_vals);

    const int gemm_grid = (NN + 127) / 128;
    const int spmm_grid = (NN * 32 + 255) / 256;

    // layer 1: S = X @ W1; H = relu(A @ S + b1)
    sgemm_n128<FIN><<<gemm_grid, 256>>>(features, W1, dS, NN);
    spmm_relu_kernel<<<spmm_grid, 256>>>(dS, b1, dH);

    // layer 2: S = H @ W2; out = relu(A @ S + b2)
    sgemm_n128<HD><<<gemm_grid, 256>>>(dH, W2, dS, NN);
    spmm_relu_kernel<<<spmm_grid, 256>>>(dS, b2, out);
}

// round 2
// speedup vs baseline: 1.0013x; 1.0013x over previous
#include <cuda_runtime.h>
#include <cstdint>

#define NN 50000
#define NE 800000
#define FIN 256
#define HD 128

// ---------------- scratch (no allocations allowed) ----------------
__device__ float g_S[(size_t)NN * HD];   // support buffer (X@W or H@W)
__device__ float g_H[(size_t)NN * HD];   // hidden layer output
__device__ int   g_rowptr[NN + 1];
__device__ int   g_fill[NN];
__device__ int   g_col[NE];
__device__ float g_val[NE];

// ---------------- CSR build ----------------
__global__ void zero_rowptr_kernel() {
    int i = blockIdx.x * blockDim.x + threadIdx.x;
    if (i <= NN) g_rowptr[i] = 0;
}

__global__ void hist_kernel(const int* __restrict__ rows) {
    int e = blockIdx.x * blockDim.x + threadIdx.x;
    if (e < NE) atomicAdd(&g_rowptr[rows[e] + 1], 1);
}

// single-block inclusive scan over g_rowptr[0..NN]; also writes g_fill[r]=rowptr[r]
__global__ void scan_kernel() {
    __shared__ int warp_sums[32];
    __shared__ int s_carry;
    const int tid = threadIdx.x;
    const int lane = tid & 31;
    const int wid = tid >> 5;
    if (tid == 0) s_carry = 0;
    __syncthreads();
    for (int base = 0; base < NN + 1; base += 1024) {
        int i = base + tid;
        int v = (i <= NN) ? g_rowptr[i] : 0;
        int x = v;
        #pragma unroll
        for (int off = 1; off < 32; off <<= 1) {
            int t = __shfl_up_sync(0xffffffffu, x, off);
            if (lane >= off) x += t;
        }
        if (lane == 31) warp_sums[wid] = x;
        __syncthreads();
        if (wid == 0) {
            int w = warp_sums[lane];
            #pragma unroll
            for (int off = 1; off < 32; off <<= 1) {
                int t = __shfl_up_sync(0xffffffffu, w, off);
                if (lane >= off) w += t;
            }
            warp_sums[lane] = w;
        }
        __syncthreads();
        int prefix = (wid > 0 ? warp_sums[wid - 1] : 0) + s_carry;
        int out = x + prefix;  // inclusive scan value at i == rowptr[i]
        if (i <= NN) {
            g_rowptr[i] = out;
            if (i < NN) g_fill[i] = out;  // start cursor for scatter
        }
        __syncthreads();
        if (tid == 1023) s_carry = out;
        __syncthreads();
    }
}

__global__ void scatter_kernel(const int* __restrict__ rows,
                               const int* __restrict__ cols,
                               const float* __restrict__ vals) {
    int e = blockIdx.x * blockDim.x + threadIdx.x;
    if (e < NE) {
        int r = rows[e];
        int p = atomicAdd(&g_fill[r], 1);
        g_col[p] = cols[e];
        g_val[p] = vals[e];
    }
}

// ---------------- dense GEMM: C[M x 128] = A[M x K] @ B[K x 128] ----------------
// 128x128 block tile, BK=16, 256 threads, 8x8 per-thread micro-tile
template <int K>
__global__ __launch_bounds__(256, 2)
void sgemm_n128(const float* __restrict__ A, const float* __restrict__ B,
                float* __restrict__ C, int M) {
    __shared__ float As[16][128];
    __shared__ float Bs[16][128];
    const int tid = threadIdx.x;
    const int tx = tid & 15;        // 0..15 -> 8 cols each
    const int ty = tid >> 4;        // 0..15 -> 8 rows each
    const int m0 = blockIdx.x * 128;

    float acc[8][8];
    #pragma unroll
    for (int i = 0; i < 8; i++)
        #pragma unroll
        for (int j = 0; j < 8; j++) acc[i][j] = 0.f;

    for (int kb = 0; kb < K; kb += 16) {
        // load A tile (128 rows x 16 cols), transpose into As[k][m]
        #pragma unroll
        for (int l = 0; l < 2; l++) {
            int f = tid + l * 256;      // 0..511 float4s
            int row = f >> 2;           // 0..127
            int c4 = f & 3;             // 0..3
            int gm = m0 + row;
            float4 v = make_float4(0.f, 0.f, 0.f, 0.f);
            if (gm < M) v = *(const float4*)(A + (size_t)gm * K + kb + c4 * 4);
            As[c4 * 4 + 0][row] = v.x;
            As[c4 * 4 + 1][row] = v.y;
            As[c4 * 4 + 2][row] = v.z;
            As[c4 * 4 + 3][row] = v.w;
        }
        // load B tile (16 rows x 128 cols)
        #pragma unroll
        for (int l = 0; l < 2; l++) {
            int f = tid + l * 256;      // 0..511 float4s
            int row = f >> 5;           // 0..15
            int c = f & 31;             // 0..31
            *(float4*)&Bs[row][c * 4] =
                *(const float4*)(B + (size_t)(kb + row) * 128 + c * 4);
        }
        __syncthreads();
        #pragma unroll
        for (int kk = 0; kk < 16; kk++) {
            float a[8], b[8];
            float4 a0 = *(const float4*)&As[kk][ty * 8];
            float4 a1 = *(const float4*)&As[kk][ty * 8 + 4];
            float4 b0 = *(const float4*)&Bs[kk][tx * 8];
            float4 b1 = *(const float4*)&Bs[kk][tx * 8 + 4];
            a[0]=a0.x; a[1]=a0.y; a[2]=a0.z; a[3]=a0.w;
            a[4]=a1.x; a[5]=a1.y; a[6]=a1.z; a[7]=a1.w;
            b[0]=b0.x; b[1]=b0.y; b[2]=b0.z; b[3]=b0.w;
            b[4]=b1.x; b[5]=b1.y; b[6]=b1.z; b[7]=b1.w;
            #pragma unroll
            for (int i = 0; i < 8; i++)
                #pragma unroll
                for (int j = 0; j < 8; j++)
                    acc[i][j] += a[i] * b[j];
        }
        __syncthreads();
    }
    // store
    #pragma unroll
    for (int i = 0; i < 8; i++) {
        int gm = m0 + ty * 8 + i;
        if (gm < M) {
            *(float4*)&C[(size_t)gm * 128 + tx * 8] =
                make_float4(acc[i][0], acc[i][1], acc[i][2], acc[i][3]);
            *(float4*)&C[(size_t)gm * 128 + tx * 8 + 4] =
                make_float4(acc[i][4], acc[i][5], acc[i][6], acc[i][7]);
        }
    }
}

// ---------------- SPMM (CSR gather) + bias + relu ----------------
// one warp per row, float4 per lane (32 lanes x 4 = 128 cols)
__global__ __launch_bounds__(256)
void spmm_relu_kernel(const float* __restrict__ S, const float* __restrict__ bias,
                      float* __restrict__ out) {
    int gw = (blockIdx.x * blockDim.x + threadIdx.x) >> 5;
    int lane = threadIdx.x & 31;
    if (gw >= NN) return;
    int s = g_rowptr[gw];
    int e = g_rowptr[gw + 1];
    float4 a0 = make_float4(0.f, 0.f, 0.f, 0.f);
    float4 a1 = make_float4(0.f, 0.f, 0.f, 0.f);
    int i = s;
    for (; i + 2 <= e; i += 2) {
        int c0 = g_col[i];
        int c1 = g_col[i + 1];
        float v0 = g_val[i];
        float v1 = g_val[i + 1];
        float4 x0 = *(const float4*)(S + (size_t)c0 * 128 + lane * 4);
        float4 x1 = *(const float4*)(S + (size_t)c1 * 128 + lane * 4);
        a0.x += v0 * x0.x; a0.y += v0 * x0.y; a0.z += v0 * x0.z; a0.w += v0 * x0.w;
        a1.x += v1 * x1.x; a1.y += v1 * x1.y; a1.z += v1 * x1.z; a1.w += v1 * x1.w;
    }
    if (i < e) {
        int c0 = g_col[i];
        float v0 = g_val[i];
        float4 x0 = *(const float4*)(S + (size_t)c0 * 128 + lane * 4);
        a0.x += v0 * x0.x; a0.y += v0 * x0.y; a0.z += v0 * x0.z; a0.w += v0 * x0.w;
    }
    float4 b = *(const float4*)(bias + lane * 4);
    float4 r;
    r.x = fmaxf(a0.x + a1.x + b.x, 0.f);
    r.y = fmaxf(a0.y + a1.y + b.y, 0.f);
    r.z = fmaxf(a0.z + a1.z + b.z, 0.f);
    r.w = fmaxf(a0.w + a1.w + b.w, 0.f);
    *(float4*)(out + (size_t)gw * 128 + lane * 4) = r;
}

// ---------------- launch ----------------
extern "C" void kernel_launch(void* const* d_in, const int* in_sizes, int n_in,
                              void* d_out, int out_size) {
    const float* features = (const float*)d_in[0];
    const int*   adj_rows = (const int*)d_in[1];
    const int*   adj_cols = (const int*)d_in[2];
    const float* adj_vals = (const float*)d_in[3];
    const float* W1 = (const float*)d_in[4];
    const float* b1 = (const float*)d_in[5];
    const float* W2 = (const float*)d_in[6];
    const float* b2 = (const float*)d_in[7];
    float* out = (float*)d_out;

    float* dS;  cudaGetSymbolAddress((void**)&dS, g_S);
    float* dH;  cudaGetSymbolAddress((void**)&dH, g_H);

    // CSR build
    zero_rowptr_kernel<<<(NN + 1 + 255) / 256, 256>>>();
    hist_kernel<<<(NE + 255) / 256, 256>>>(adj_rows);
    scan_kernel<<<1, 1024>>>();
    scatter_kernel<<<(NE + 255) / 256, 256>>>(adj_rows, adj_cols, adj_vals);

    const int gemm_grid = (NN + 127) / 128;
    const int spmm_grid = (NN * 32 + 255) / 256;

    // layer 1: S = X @ W1; H = relu(A @ S + b1)
    sgemm_n128<FIN><<<gemm_grid, 256>>>(features, W1, dS, NN);
    spmm_relu_kernel<<<spmm_grid, 256>>>(dS, b1, dH);

    // layer 2: S = H @ W2; out = relu(A @ S + b2)
    sgemm_n128<HD><<<gemm_grid, 256>>>(dH, W2, dS, NN);
    spmm_relu_kernel<<<spmm_grid, 256>>>(dS, b2, out);
}